// round 7
// baseline (speedup 1.0000x reference)
#include <cuda_runtime.h>
#include <math.h>
#include <stdint.h>

#define BB 32
#define TT 200
#define EE 32
#define HH 128
#define VV 8000
#define MM (BB*TT)            // 6400
#define NT63 63               // n tiles of 128
#define MT128 50              // m tiles of 128
#define TOTTILES (NT63*MT128) // 3150

// Scratch (device globals)
__device__ float g_ux[MM*HH];              // [m][h]
__device__ float g_Afrag[100*8192];        // A frags: 64-row chunks, R3 layout (tf32)
__device__ float g_Bfrag[NT63*16384];      // B frags: 128-col tiles, R3 layout (tf32)

// ---------------------------------------------------------------------------
__device__ __forceinline__ float to_tf32(float x) {
    unsigned u;
    asm("cvt.rna.tf32.f32 %0, %1;" : "=r"(u) : "f"(x));
    return __uint_as_float(u);
}
__device__ __forceinline__ void mma8(float c[4], const float4& a, float bx, float by) {
    asm("mma.sync.aligned.m16n8k8.row.col.f32.tf32.tf32.f32 "
        "{%0,%1,%2,%3},{%4,%5,%6,%7},{%8,%9},{%0,%1,%2,%3};"
        : "+f"(c[0]), "+f"(c[1]), "+f"(c[2]), "+f"(c[3])
        : "r"(__float_as_uint(a.x)), "r"(__float_as_uint(a.y)),
          "r"(__float_as_uint(a.z)), "r"(__float_as_uint(a.w)),
          "r"(__float_as_uint(bx)), "r"(__float_as_uint(by)));
}
__device__ __forceinline__ void cpa16(uint32_t s, const void* g) {
    asm volatile("cp.async.ca.shared.global [%0], [%1], 16;" :: "r"(s), "l"(g));
}
__device__ __forceinline__ void cp_commit() {
    asm volatile("cp.async.commit_group;");
}
__device__ __forceinline__ void cp_wait1() {
    asm volatile("cp.async.wait_group 1;");
}
__device__ __forceinline__ void cp_wait0() {
    asm volatile("cp.async.wait_group 0;");
}

// ---------------------------------------------------------------------------
// Fused prep kernel: blocks 0..62 shuffle Vw into B-frag layout (R3 verified);
// blocks 63..262 compute ux (R3 verified).
// ---------------------------------------------------------------------------
__global__ void k_prep(const float* __restrict__ Vw, const float* __restrict__ x,
                       const float* __restrict__ Uw, const float* __restrict__ Ub,
                       const float* __restrict__ Wb) {
    extern __shared__ float dynsm[];
    int tid = threadIdx.x;
    if (blockIdx.x < NT63) {
        // ---- prepB ----
        float* Bs = dynsm;                   // 16384 floats
        int nt = blockIdx.x;
        int n0 = nt * 128;
        #pragma unroll
        for (int i = 0; i < 16; i++) {
            int f  = tid + i * 256;
            int nn = f >> 5;
            int c4 = f & 31;
            int gn = n0 + nn;
            float4 v = (gn < VV) ? ((const float4*)Vw)[(size_t)gn * 32 + c4]
                                 : make_float4(0.f, 0.f, 0.f, 0.f);
            int k0 = c4 * 4;
            int kg = k0 >> 3, ip = nn >> 4;
            int reg  = ((nn >> 3) & 1) * 2 + ((k0 & 7) >> 2);
            int base = (kg * 8 + ip) * 128 + ((nn & 7) << 2) * 4 + reg;
            Bs[base + 0]  = to_tf32(v.x);
            Bs[base + 4]  = to_tf32(v.y);
            Bs[base + 8]  = to_tf32(v.z);
            Bs[base + 12] = to_tf32(v.w);
        }
        __syncthreads();
        float4* dst = (float4*)g_Bfrag + (size_t)nt * 4096;
        #pragma unroll
        for (int i = 0; i < 16; i++)
            dst[tid + i * 256] = ((float4*)Bs)[tid + i * 256];
    } else {
        // ---- ux ----
        __shared__ float UwT[EE][HH];
        __shared__ float xs[32][EE];
        __shared__ float bias[HH];
        for (int f = tid; f < HH * EE / 4; f += 256) {
            int h = f / (EE / 4), c = f % (EE / 4);
            float4 u = ((const float4*)Uw)[f];
            UwT[c * 4 + 0][h] = u.x;
            UwT[c * 4 + 1][h] = u.y;
            UwT[c * 4 + 2][h] = u.z;
            UwT[c * 4 + 3][h] = u.w;
        }
        if (tid < HH) bias[tid] = Ub[tid] + Wb[tid];
        int m0 = (blockIdx.x - NT63) * 32;
        {
            int r = tid / 8, c = tid % 8;
            ((float4*)&xs[r][0])[c] = ((const float4*)x)[(size_t)(m0 + r) * (EE / 4) + c];
        }
        __syncthreads();
        int h = tid % HH;
        int half = tid / HH;
        #pragma unroll
        for (int rr = 0; rr < 16; rr++) {
            int r = half * 16 + rr;
            float acc = bias[h];
            const float4* xv = (const float4*)&xs[r][0];
            #pragma unroll
            for (int e4 = 0; e4 < EE / 4; e4++) {
                float4 xf = xv[e4];
                acc += UwT[e4 * 4 + 0][h] * xf.x;
                acc += UwT[e4 * 4 + 1][h] * xf.y;
                acc += UwT[e4 * 4 + 2][h] * xf.z;
                acc += UwT[e4 * 4 + 3][h] * xf.w;
            }
            g_ux[(size_t)(m0 + r) * HH + h] = acc;
        }
    }
}

// ---------------------------------------------------------------------------
// Recurrence: 512 threads, 4 threads per j, Ww register-resident.
// Stores hs in A-fragment layout (R3 verified formulas).
// ---------------------------------------------------------------------------
__global__ void __launch_bounds__(512, 1)
k_rnn(const float* __restrict__ Ww, float* __restrict__ out_hidden) {
    __shared__ float hb[2][HH];
    int tid = threadIdx.x;
    int j   = tid >> 2;
    int q   = tid & 3;
    int b   = blockIdx.x;

    // Each thread owns 32 consecutive Ww[j][k] values (8 float4)
    float4 w[8];
    const float4* Ww4 = (const float4*)Ww;
    #pragma unroll
    for (int i = 0; i < 8; i++)
        w[i] = Ww4[(size_t)j * 32 + q * 8 + i];

    if (tid < HH) hb[0][tid] = 0.0f;
    __syncthreads();

    const float* uxb = g_ux + (size_t)b * TT * HH;

    // A-frag index pieces depending only on j (k = j)  [R3 verified]
    int kg = j >> 3, kl = j & 7;
    int kcol = (kl & 3) * 4 + 2 * (kl >> 2);

    int p = 0;
    float v = 0.0f;
    for (int t = 0; t < TT; t++) {
        const float4* h4 = (const float4*)hb[p] + q * 8;
        float a = 0.f, b2 = 0.f, c = 0.f, d = 0.f;
        #pragma unroll
        for (int i = 0; i < 8; i++) {
            float4 hv = h4[i];
            a  += w[i].x * hv.x;
            b2 += w[i].y * hv.y;
            c  += w[i].z * hv.z;
            d  += w[i].w * hv.w;
        }
        float acc = (a + b2) + (c + d);
        acc += __shfl_xor_sync(0xFFFFFFFFu, acc, 1);
        acc += __shfl_xor_sync(0xFFFFFFFFu, acc, 2);
        if (q == 0) {
            v = tanhf(acc + uxb[t * HH + j]);
            hb[1 - p][j] = v;
            int m  = b * TT + t;
            int mt = m >> 6, mr = m & 63;
            int im = mr >> 4, r = mr & 15;
            int idx = mt * 8192 + (kg * 4 + im) * 128
                    + ((r & 7) << 4) + kcol + (r >> 3);
            g_Afrag[idx] = to_tf32(v);
        }
        __syncthreads();
        p ^= 1;
    }
    if (q == 0) out_hidden[b * HH + j] = v;
}

// ---------------------------------------------------------------------------
// Persistent output GEMM (mma.sync tf32): BM=128, BN=128, K=128 resident.
// B double-buffered via cp.async; A reloaded on mt-boundary only.
// SMEM float4 offsets: A[0..4096), B0[4096..8192), B1[8192..12288)
// ---------------------------------------------------------------------------
__global__ void __launch_bounds__(256, 1)
k_gemm(const float* __restrict__ Vb, float* __restrict__ out) {
    extern __shared__ float4 sm4[];
    uint32_t smb = (uint32_t)__cvta_generic_to_shared(sm4);
    int tid  = threadIdx.x;
    int warp = tid >> 5;
    int lane = tid & 31;
    int bid  = blockIdx.x;

    int cnt   = 21 + (bid < 42);
    int start = bid * 21 + (bid < 42 ? bid : 42);

    int curr_mt = start / 63;
    // prologue: A(curr_mt) + B(start) into buf0
    {
        const float4* a4 = (const float4*)g_Afrag + (size_t)curr_mt * 4096;
        const float4* b4 = (const float4*)g_Bfrag + (size_t)(start % 63) * 4096;
        #pragma unroll
        for (int i = 0; i < 16; i++)
            cpa16(smb + (0 + tid + i * 256) * 16, a4 + tid + i * 256);
        #pragma unroll
        for (int i = 0; i < 16; i++)
            cpa16(smb + (4096 + tid + i * 256) * 16, b4 + tid + i * 256);
        cp_commit();
    }

    int wm = warp >> 2;   // 0..1  (64-row chunk)
    int wn = warp & 3;    // 0..3  (32-col group)

    for (int it = 0; it < cnt; it++) {
        int tile = start + it;
        int mt = tile / 63, nt = tile % 63;

        if (mt != curr_mt) {     // boundary: reload A (rare, compute already synced)
            const float4* a4 = (const float4*)g_Afrag + (size_t)mt * 4096;
            #pragma unroll
            for (int i = 0; i < 16; i++)
                cpa16(smb + (0 + tid + i * 256) * 16, a4 + tid + i * 256);
            cp_commit();
            curr_mt = mt;
        }
        if (it + 1 < cnt) {      // prefetch next B
            int ntile = tile + 1;
            const float4* b4 = (const float4*)g_Bfrag + (size_t)(ntile % 63) * 4096;
            uint32_t dst = smb + ((((it + 1) & 1) ? 8192 : 4096)) * 16;
            #pragma unroll
            for (int i = 0; i < 16; i++)
                cpa16(dst + (tid + i * 256) * 16, b4 + tid + i * 256);
            cp_commit();
            cp_wait1();          // everything except newest group done
        } else {
            cp_wait0();
        }
        __syncthreads();

        const float4* As4 = sm4;
        const float4* Bs4 = sm4 + ((it & 1) ? 8192 : 4096);

        float c[4][4][4];
        #pragma unroll
        for (int a = 0; a < 4; a++)
            #pragma unroll
            for (int b = 0; b < 4; b++)
                #pragma unroll
                for (int d = 0; d < 4; d++) c[a][b][d] = 0.0f;

        #pragma unroll
        for (int kg = 0; kg < 16; kg++) {
            float4 av[4];
            #pragma unroll
            for (int im = 0; im < 4; im++)
                av[im] = As4[wm * 2048 + (kg * 4 + im) * 32 + lane];
            float4 b0 = Bs4[(kg * 8 + wn * 2 + 0) * 32 + lane];
            float4 b1 = Bs4[(kg * 8 + wn * 2 + 1) * 32 + lane];
            #pragma unroll
            for (int im = 0; im < 4; im++) {
                mma8(c[im][0], av[im], b0.x, b0.y);
                mma8(c[im][1], av[im], b0.z, b0.w);
                mma8(c[im][2], av[im], b1.x, b1.y);
                mma8(c[im][3], av[im], b1.z, b1.w);
            }
        }

        // epilogue: direct float2 stores (R3-verified mapping)
        int m0 = mt * 128 + wm * 64;
        int n0 = nt * 128 + wn * 32;
        #pragma unroll
        for (int nt4 = 0; nt4 < 4; nt4++) {
            int col = n0 + nt4 * 8 + (lane & 3) * 2;
            if (col < VV) {
                float vbx = Vb[col], vby = Vb[col + 1];
                #pragma unroll
                for (int im = 0; im < 4; im++) {
                    int row = m0 + im * 16 + (lane >> 2);
                    float2 o0 = make_float2(c[im][nt4][0] + vbx, c[im][nt4][1] + vby);
                    float2 o1 = make_float2(c[im][nt4][2] + vbx, c[im][nt4][3] + vby);
                    *(float2*)(out + (size_t)row * VV + col) = o0;
                    *(float2*)(out + (size_t)(row + 8) * VV + col) = o1;
                }
            }
        }
        __syncthreads();   // protect buffers before next iteration's prefetch
    }
}

// ---------------------------------------------------------------------------
extern "C" void kernel_launch(void* const* d_in, const int* in_sizes, int n_in,
                              void* d_out, int out_size) {
    const float* x  = (const float*)d_in[0];
    const float* Ww = (const float*)d_in[1];
    const float* Wb = (const float*)d_in[2];
    const float* Uw = (const float*)d_in[3];
    const float* Ub = (const float*)d_in[4];
    const float* Vw = (const float*)d_in[5];
    const float* Vb = (const float*)d_in[6];
    float* out = (float*)d_out;

    cudaFuncSetAttribute(k_prep, cudaFuncAttributeMaxDynamicSharedMemorySize, 65536);
    cudaFuncSetAttribute(k_gemm, cudaFuncAttributeMaxDynamicSharedMemorySize,
                         12288 * 16);   // 192 KB

    k_prep<<<NT63 + MM / 32, 256, 65536>>>(Vw, x, Uw, Ub, Wb);
    k_rnn<<<BB, 512>>>(Ww, out + (size_t)MM * VV);
    k_gemm<<<148, 256, 12288 * 16>>>(Vb, out);
}

// round 8
// speedup vs baseline: 1.0416x; 1.0416x over previous
#include <cuda_runtime.h>
#include <math.h>
#include <stdint.h>

#define BB 32
#define TT 200
#define EE 32
#define HH 128
#define VV 8000
#define MM (BB*TT)            // 6400
#define NT63 63               // n-tiles of 128
#define MT 100                // m-tiles of 64

// Scratch (device globals)
__device__ float g_Afrag[MT*16*4*128];   // A fragments, tf32 (3.3 MB)
__device__ float g_Bfrag[NT63*16*8*128]; // B fragments, tf32 (4.1 MB)

// ---------------------------------------------------------------------------
__device__ __forceinline__ float to_tf32(float x) {
    unsigned u;
    asm("cvt.rna.tf32.f32 %0, %1;" : "=r"(u) : "f"(x));
    return __uint_as_float(u);
}
__device__ __forceinline__ void mma8(float c[4], const float4& a, float bx, float by) {
    asm("mma.sync.aligned.m16n8k8.row.col.f32.tf32.tf32.f32 "
        "{%0,%1,%2,%3},{%4,%5,%6,%7},{%8,%9},{%0,%1,%2,%3};"
        : "+f"(c[0]), "+f"(c[1]), "+f"(c[2]), "+f"(c[3])
        : "r"(__float_as_uint(a.x)), "r"(__float_as_uint(a.y)),
          "r"(__float_as_uint(a.z)), "r"(__float_as_uint(a.w)),
          "r"(__float_as_uint(bx)), "r"(__float_as_uint(by)));
}
__device__ __forceinline__ void cpa16(uint32_t s, const void* g) {
    asm volatile("cp.async.ca.shared.global [%0], [%1], 16;" :: "r"(s), "l"(g));
}

// ---------------------------------------------------------------------------
// prepB: shuffle Vw [V,H] into B-fragment layout (tf32). [R3 verified]
// ---------------------------------------------------------------------------
__global__ void k_prepB(const float* __restrict__ Vw) {
    extern __shared__ float Bs[];          // 16384 floats (64 KB)
    int nt = blockIdx.x, tid = threadIdx.x;
    int n0 = nt * 128;
    #pragma unroll
    for (int i = 0; i < 16; i++) {
        int f  = tid + i * 256;
        int nn = f >> 5;
        int c4 = f & 31;
        int gn = n0 + nn;
        float4 v = (gn < VV) ? ((const float4*)Vw)[(size_t)gn * 32 + c4]
                             : make_float4(0.f, 0.f, 0.f, 0.f);
        int k0 = c4 * 4;
        int kg = k0 >> 3, ip = nn >> 4;
        int reg  = ((nn >> 3) & 1) * 2 + ((k0 & 7) >> 2);
        int base = (kg * 8 + ip) * 128 + ((nn & 7) << 2) * 4 + reg;
        Bs[base + 0]  = to_tf32(v.x);
        Bs[base + 4]  = to_tf32(v.y);
        Bs[base + 8]  = to_tf32(v.z);
        Bs[base + 12] = to_tf32(v.w);
    }
    __syncthreads();
    float4* dst = (float4*)g_Bfrag + (size_t)nt * 4096;
    #pragma unroll
    for (int i = 0; i < 16; i++)
        dst[tid + i * 256] = ((float4*)Bs)[tid + i * 256];
}

// ---------------------------------------------------------------------------
// Fused RNN: per-batch block (512 threads).
// Prologue: ux[t][h] for the whole batch into SMEM.
// Recurrence: 4 threads/j, Ww register-resident, ux from SMEM.
// Stores hs in A-fragment layout. [rnn core + scatter: R7 verified]
// ---------------------------------------------------------------------------
// SMEM float offsets
#define S_UX   0                       // 200*128 = 25600
#define S_XS   (S_UX + TT*HH)          // 200*32  = 6400
#define S_UWT  (S_XS + TT*EE)          // 32*128  = 4096
#define S_BIAS (S_UWT + EE*HH)         // 128
#define S_HB   (S_BIAS + HH)           // 2*128
#define S_RNN_TOT (S_HB + 2*HH)        // 36608 floats = 146432 B

__global__ void __launch_bounds__(512, 1)
k_rnn(const float* __restrict__ x, const float* __restrict__ Uw,
      const float* __restrict__ Ub, const float* __restrict__ Wb,
      const float* __restrict__ Ww, float* __restrict__ out_hidden) {
    extern __shared__ float sm[];
    float* uxs  = sm + S_UX;
    float* xs   = sm + S_XS;
    float* UwT  = sm + S_UWT;
    float* bias = sm + S_BIAS;
    float* hb   = sm + S_HB;

    int tid = threadIdx.x;
    int b   = blockIdx.x;

    // ---- load Uw transposed + bias + x rows ----
    for (int f = tid; f < HH * EE / 4; f += 512) {
        int h = f / (EE / 4), c = f % (EE / 4);
        float4 u = ((const float4*)Uw)[f];
        UwT[(c * 4 + 0) * HH + h] = u.x;
        UwT[(c * 4 + 1) * HH + h] = u.y;
        UwT[(c * 4 + 2) * HH + h] = u.z;
        UwT[(c * 4 + 3) * HH + h] = u.w;
    }
    if (tid < HH) bias[tid] = Ub[tid] + Wb[tid];
    // x[b]: 200*32 floats = 1600 float4
    const float4* xb4 = (const float4*)(x + (size_t)b * TT * EE);
    for (int f = tid; f < TT * EE / 4; f += 512)
        ((float4*)xs)[f] = xb4[f];
    if (tid < HH) hb[tid] = 0.0f;
    __syncthreads();

    // ---- prologue: ux for all timesteps ----
    for (int idx = tid; idx < TT * HH; idx += 512) {
        int t = idx >> 7, h = idx & 127;
        float acc = bias[h];
        const float4* xv = (const float4*)(xs + t * EE);
        #pragma unroll
        for (int e4 = 0; e4 < EE / 4; e4++) {
            float4 xf = xv[e4];
            acc += UwT[(e4 * 4 + 0) * HH + h] * xf.x;
            acc += UwT[(e4 * 4 + 1) * HH + h] * xf.y;
            acc += UwT[(e4 * 4 + 2) * HH + h] * xf.z;
            acc += UwT[(e4 * 4 + 3) * HH + h] * xf.w;
        }
        uxs[idx] = acc;
    }

    // ---- recurrence ----
    int j = tid >> 2;
    int q = tid & 3;

    float4 w[8];
    const float4* Ww4 = (const float4*)Ww;
    #pragma unroll
    for (int i = 0; i < 8; i++)
        w[i] = Ww4[(size_t)j * 32 + q * 8 + i];

    // A-frag index pieces depending only on j (k = j)  [verified]
    int kg = j >> 3, kl = j & 7;
    int kcol = (kl & 3) * 4 + 2 * (kl >> 2);

    __syncthreads();

    int p = 0;
    float v = 0.0f;
    for (int t = 0; t < TT; t++) {
        const float4* h4 = (const float4*)(hb + p * HH) + q * 8;
        float a = 0.f, b2 = 0.f, c = 0.f, d = 0.f;
        #pragma unroll
        for (int i = 0; i < 8; i++) {
            float4 hv = h4[i];
            a  += w[i].x * hv.x;
            b2 += w[i].y * hv.y;
            c  += w[i].z * hv.z;
            d  += w[i].w * hv.w;
        }
        float acc = (a + b2) + (c + d);
        acc += __shfl_xor_sync(0xFFFFFFFFu, acc, 1);
        acc += __shfl_xor_sync(0xFFFFFFFFu, acc, 2);
        if (q == 0) {
            v = tanhf(acc + uxs[t * HH + j]);
            hb[(1 - p) * HH + j] = v;
            int m  = b * TT + t;
            int mt = m >> 6, mr = m & 63;
            int im = mr >> 4, r = mr & 15;
            int idx = mt * 8192 + (kg * 4 + im) * 128
                    + ((r & 7) << 4) + kcol + (r >> 3);
            g_Afrag[idx] = to_tf32(v);
        }
        __syncthreads();
        p ^= 1;
    }
    if (q == 0) out_hidden[b * HH + j] = v;
}

// ---------------------------------------------------------------------------
// Output GEMM: EXACT R3 version (verified 113.5us).
// BM=64, BN=128, K=128 resident; 8 warps (2M x 4N), warp does 32x32.
// ---------------------------------------------------------------------------
__global__ void __launch_bounds__(256, 2)
k_gemm(const float* __restrict__ Vb, float* __restrict__ out) {
    extern __shared__ float sm[];
    float* As = sm;                 // 8192 floats (32 KB)
    float* Bs = sm + 8192;          // 16384 floats (64 KB)

    int tid  = threadIdx.x;
    int warp = tid >> 5;
    int lane = tid & 31;
    int mt = blockIdx.y, nt = blockIdx.x;
    int m0 = mt * 64, n0 = nt * 128;

    const float4* Asrc = (const float4*)g_Afrag + (size_t)mt * 2048;
    const float4* Bsrc = (const float4*)g_Bfrag + (size_t)nt * 4096;
    uint32_t sA = (uint32_t)__cvta_generic_to_shared(As);
    uint32_t sB = (uint32_t)__cvta_generic_to_shared(Bs);
    #pragma unroll
    for (int i = 0; i < 8; i++)
        cpa16(sA + (tid + i * 256) * 16, Asrc + tid + i * 256);
    #pragma unroll
    for (int i = 0; i < 16; i++)
        cpa16(sB + (tid + i * 256) * 16, Bsrc + tid + i * 256);
    asm volatile("cp.async.commit_group;");
    asm volatile("cp.async.wait_group 0;");
    __syncthreads();

    int wm = warp >> 2;   // 0..1
    int wn = warp & 3;    // 0..3

    float c[2][4][4];
    #pragma unroll
    for (int a = 0; a < 2; a++)
        #pragma unroll
        for (int b = 0; b < 4; b++)
            #pragma unroll
            for (int d = 0; d < 4; d++) c[a][b][d] = 0.0f;

    const float4* As4 = (const float4*)As;
    const float4* Bs4 = (const float4*)Bs;

    #pragma unroll
    for (int kg = 0; kg < 16; kg++) {
        float4 a0 = As4[(kg * 4 + wm * 2 + 0) * 32 + lane];
        float4 a1 = As4[(kg * 4 + wm * 2 + 1) * 32 + lane];
        float4 b0 = Bs4[(kg * 8 + wn * 2 + 0) * 32 + lane];
        float4 b1 = Bs4[(kg * 8 + wn * 2 + 1) * 32 + lane];
        mma8(c[0][0], a0, b0.x, b0.y);
        mma8(c[0][1], a0, b0.z, b0.w);
        mma8(c[0][2], a0, b1.x, b1.y);
        mma8(c[0][3], a0, b1.z, b1.w);
        mma8(c[1][0], a1, b0.x, b0.y);
        mma8(c[1][1], a1, b0.z, b0.w);
        mma8(c[1][2], a1, b1.x, b1.y);
        mma8(c[1][3], a1, b1.z, b1.w);
    }

    #pragma unroll
    for (int im = 0; im < 2; im++) {
        int row = m0 + wm * 32 + im * 16 + (lane >> 2);
        #pragma unroll
        for (int ntile = 0; ntile < 4; ntile++) {
            int col = n0 + wn * 32 + ntile * 8 + (lane & 3) * 2;
            if (col < VV) {
                float vbx = Vb[col], vby = Vb[col + 1];
                float2 o0 = make_float2(c[im][ntile][0] + vbx, c[im][ntile][1] + vby);
                float2 o1 = make_float2(c[im][ntile][2] + vbx, c[im][ntile][3] + vby);
                *(float2*)(out + (size_t)row * VV + col) = o0;
                *(float2*)(out + (size_t)(row + 8) * VV + col) = o1;
            }
        }
    }
}

// ---------------------------------------------------------------------------
extern "C" void kernel_launch(void* const* d_in, const int* in_sizes, int n_in,
                              void* d_out, int out_size) {
    const float* x  = (const float*)d_in[0];
    const float* Ww = (const float*)d_in[1];
    const float* Wb = (const float*)d_in[2];
    const float* Uw = (const float*)d_in[3];
    const float* Ub = (const float*)d_in[4];
    const float* Vw = (const float*)d_in[5];
    const float* Vb = (const float*)d_in[6];
    float* out = (float*)d_out;

    cudaFuncSetAttribute(k_prepB, cudaFuncAttributeMaxDynamicSharedMemorySize, 65536);
    cudaFuncSetAttribute(k_rnn,   cudaFuncAttributeMaxDynamicSharedMemorySize,
                         S_RNN_TOT * 4);
    cudaFuncSetAttribute(k_gemm,  cudaFuncAttributeMaxDynamicSharedMemorySize,
                         (8192 + 16384) * 4);

    k_prepB<<<NT63, 256, 65536>>>(Vw);
    k_rnn<<<BB, 512, S_RNN_TOT * 4>>>(x, Uw, Ub, Wb, Ww, out + (size_t)MM * VV);
    k_gemm<<<dim3(NT63, MT), 256, (8192 + 16384) * 4>>>(Vb, out);
}

// round 9
// speedup vs baseline: 2.0212x; 1.9404x over previous
#include <cuda_runtime.h>
#include <math.h>
#include <stdint.h>

#define BB 32
#define TT 200
#define EE 32
#define HH 128
#define VV 8000
#define MM (BB*TT)            // 6400
#define NT63 63               // n-tiles of 128
#define MT 100                // m-tiles of 64

// Scratch (device globals)
__device__ float g_ux[MM*HH];            // [m][h]
__device__ float g_Afrag[MT*16*4*128];   // A fragments, tf32 (3.3 MB)
__device__ float g_Bfrag[NT63*16*8*128]; // B fragments, tf32 (4.1 MB)

// ---------------------------------------------------------------------------
__device__ __forceinline__ float to_tf32(float x) {
    unsigned u;
    asm("cvt.rna.tf32.f32 %0, %1;" : "=r"(u) : "f"(x));
    return __uint_as_float(u);
}
__device__ __forceinline__ float tanh_fast(float x) {
    float r;
    asm("tanh.approx.f32 %0, %1;" : "=f"(r) : "f"(x));
    return r;
}
__device__ __forceinline__ void mma8(float c[4], const float4& a, float bx, float by) {
    asm("mma.sync.aligned.m16n8k8.row.col.f32.tf32.tf32.f32 "
        "{%0,%1,%2,%3},{%4,%5,%6,%7},{%8,%9},{%0,%1,%2,%3};"
        : "+f"(c[0]), "+f"(c[1]), "+f"(c[2]), "+f"(c[3])
        : "r"(__float_as_uint(a.x)), "r"(__float_as_uint(a.y)),
          "r"(__float_as_uint(a.z)), "r"(__float_as_uint(a.w)),
          "r"(__float_as_uint(bx)), "r"(__float_as_uint(by)));
}
__device__ __forceinline__ void cpa16(uint32_t s, const void* g) {
    asm volatile("cp.async.ca.shared.global [%0], [%1], 16;" :: "r"(s), "l"(g));
}

// ---------------------------------------------------------------------------
// Fused prep: blocks 0..62 shuffle Vw into B-frag layout; 63..262 compute ux.
// [R7 verified, 12.4us]
// ---------------------------------------------------------------------------
__global__ void k_prep(const float* __restrict__ Vw, const float* __restrict__ x,
                       const float* __restrict__ Uw, const float* __restrict__ Ub,
                       const float* __restrict__ Wb) {
    extern __shared__ float dynsm[];
    int tid = threadIdx.x;
    if (blockIdx.x < NT63) {
        float* Bs = dynsm;                   // 16384 floats
        int nt = blockIdx.x;
        int n0 = nt * 128;
        #pragma unroll
        for (int i = 0; i < 16; i++) {
            int f  = tid + i * 256;
            int nn = f >> 5;
            int c4 = f & 31;
            int gn = n0 + nn;
            float4 v = (gn < VV) ? ((const float4*)Vw)[(size_t)gn * 32 + c4]
                                 : make_float4(0.f, 0.f, 0.f, 0.f);
            int k0 = c4 * 4;
            int kg = k0 >> 3, ip = nn >> 4;
            int reg  = ((nn >> 3) & 1) * 2 + ((k0 & 7) >> 2);
            int base = (kg * 8 + ip) * 128 + ((nn & 7) << 2) * 4 + reg;
            Bs[base + 0]  = to_tf32(v.x);
            Bs[base + 4]  = to_tf32(v.y);
            Bs[base + 8]  = to_tf32(v.z);
            Bs[base + 12] = to_tf32(v.w);
        }
        __syncthreads();
        float4* dst = (float4*)g_Bfrag + (size_t)nt * 4096;
        #pragma unroll
        for (int i = 0; i < 16; i++)
            dst[tid + i * 256] = ((float4*)Bs)[tid + i * 256];
    } else {
        __shared__ float UwT[EE][HH];
        __shared__ float xs[32][EE];
        __shared__ float bias[HH];
        for (int f = tid; f < HH * EE / 4; f += 256) {
            int h = f / (EE / 4), c = f % (EE / 4);
            float4 u = ((const float4*)Uw)[f];
            UwT[c * 4 + 0][h] = u.x;
            UwT[c * 4 + 1][h] = u.y;
            UwT[c * 4 + 2][h] = u.z;
            UwT[c * 4 + 3][h] = u.w;
        }
        if (tid < HH) bias[tid] = Ub[tid] + Wb[tid];
        int m0 = (blockIdx.x - NT63) * 32;
        {
            int r = tid / 8, c = tid % 8;
            ((float4*)&xs[r][0])[c] = ((const float4*)x)[(size_t)(m0 + r) * (EE / 4) + c];
        }
        __syncthreads();
        int h = tid % HH;
        int half = tid / HH;
        #pragma unroll
        for (int rr = 0; rr < 16; rr++) {
            int r = half * 16 + rr;
            float acc = bias[h];
            const float4* xv = (const float4*)&xs[r][0];
            #pragma unroll
            for (int e4 = 0; e4 < EE / 4; e4++) {
                float4 xf = xv[e4];
                acc += UwT[e4 * 4 + 0][h] * xf.x;
                acc += UwT[e4 * 4 + 1][h] * xf.y;
                acc += UwT[e4 * 4 + 2][h] * xf.z;
                acc += UwT[e4 * 4 + 3][h] * xf.w;
            }
            g_ux[(size_t)(m0 + r) * HH + h] = acc;
        }
    }
}

// ---------------------------------------------------------------------------
// Recurrence: EXACT R3 structure (256 thr, 2/j, Ww in regs, 1 shfl) plus
// (a) ux prefetched one step ahead, (b) tanh.approx.
// ---------------------------------------------------------------------------
__global__ void __launch_bounds__(256, 1)
k_rnn(const float* __restrict__ Ww, float* __restrict__ out_hidden) {
    __shared__ float hb[2][HH];
    int tid  = threadIdx.x;
    int j    = tid >> 1;
    int half = tid & 1;
    int b    = blockIdx.x;

    float4 w[16];
    const float4* Ww4 = (const float4*)Ww;
    #pragma unroll
    for (int i = 0; i < 16; i++)
        w[i] = Ww4[(size_t)j * 32 + half * 16 + i];

    if (half == 0) hb[0][j] = 0.0f;
    __syncthreads();

    const float* uxb = g_ux + (size_t)b * TT * HH;

    // A-frag index pieces depending only on j (k = j)  [R3 verified]
    int kg = j >> 3, kl = j & 7;
    int kcol = (kl & 3) * 4 + 2 * (kl >> 2);

    float uxr = uxb[j];          // ux for t=0
    int p = 0;
    float v = 0.0f;
    for (int t = 0; t < TT; t++) {
        const float4* h4 = (const float4*)hb[p] + half * 16;
        // prefetch next step's ux early (hidden behind the FMA loop)
        int tn = (t + 1 < TT) ? t + 1 : t;
        float uxn = uxb[tn * HH + j];

        float a = 0.f, b2 = 0.f, c = 0.f, d = 0.f;
        #pragma unroll
        for (int i = 0; i < 16; i++) {
            float4 hv = h4[i];
            a  += w[i].x * hv.x;
            b2 += w[i].y * hv.y;
            c  += w[i].z * hv.z;
            d  += w[i].w * hv.w;
        }
        float acc = (a + b2) + (c + d);
        acc += __shfl_xor_sync(0xFFFFFFFFu, acc, 1);
        v = tanh_fast(acc + uxr);
        uxr = uxn;
        if (half == 0) {
            hb[1 - p][j] = v;
            int m  = b * TT + t;
            int mt = m >> 6, mr = m & 63;
            int im = mr >> 4, r = mr & 15;
            int idx = mt * 8192 + (kg * 4 + im) * 128
                    + ((r & 7) << 4) + kcol + (r >> 3);
            g_Afrag[idx] = to_tf32(v);
        }
        __syncthreads();
        p ^= 1;
    }
    if (half == 0) out_hidden[b * HH + j] = v;
}

// ---------------------------------------------------------------------------
// Output GEMM: EXACT R3 version (verified 113.5us).
// ---------------------------------------------------------------------------
__global__ void __launch_bounds__(256, 2)
k_gemm(const float* __restrict__ Vb, float* __restrict__ out) {
    extern __shared__ float sm[];
    float* As = sm;                 // 8192 floats (32 KB)
    float* Bs = sm + 8192;          // 16384 floats (64 KB)

    int tid  = threadIdx.x;
    int warp = tid >> 5;
    int lane = tid & 31;
    int mt = blockIdx.y, nt = blockIdx.x;
    int m0 = mt * 64, n0 = nt * 128;

    const float4* Asrc = (const float4*)g_Afrag + (size_t)mt * 2048;
    const float4* Bsrc = (const float4*)g_Bfrag + (size_t)nt * 4096;
    uint32_t sA = (uint32_t)__cvta_generic_to_shared(As);
    uint32_t sB = (uint32_t)__cvta_generic_to_shared(Bs);
    #pragma unroll
    for (int i = 0; i < 8; i++)
        cpa16(sA + (tid + i * 256) * 16, Asrc + tid + i * 256);
    #pragma unroll
    for (int i = 0; i < 16; i++)
        cpa16(sB + (tid + i * 256) * 16, Bsrc + tid + i * 256);
    asm volatile("cp.async.commit_group;");
    asm volatile("cp.async.wait_group 0;");
    __syncthreads();

    int wm = warp >> 2;   // 0..1
    int wn = warp & 3;    // 0..3

    float c[2][4][4];
    #pragma unroll
    for (int a = 0; a < 2; a++)
        #pragma unroll
        for (int b = 0; b < 4; b++)
            #pragma unroll
            for (int d = 0; d < 4; d++) c[a][b][d] = 0.0f;

    const float4* As4 = (const float4*)As;
    const float4* Bs4 = (const float4*)Bs;

    #pragma unroll
    for (int kg = 0; kg < 16; kg++) {
        float4 a0 = As4[(kg * 4 + wm * 2 + 0) * 32 + lane];
        float4 a1 = As4[(kg * 4 + wm * 2 + 1) * 32 + lane];
        float4 b0 = Bs4[(kg * 8 + wn * 2 + 0) * 32 + lane];
        float4 b1 = Bs4[(kg * 8 + wn * 2 + 1) * 32 + lane];
        mma8(c[0][0], a0, b0.x, b0.y);
        mma8(c[0][1], a0, b0.z, b0.w);
        mma8(c[0][2], a0, b1.x, b1.y);
        mma8(c[0][3], a0, b1.z, b1.w);
        mma8(c[1][0], a1, b0.x, b0.y);
        mma8(c[1][1], a1, b0.z, b0.w);
        mma8(c[1][2], a1, b1.x, b1.y);
        mma8(c[1][3], a1, b1.z, b1.w);
    }

    #pragma unroll
    for (int im = 0; im < 2; im++) {
        int row = m0 + wm * 32 + im * 16 + (lane >> 2);
        #pragma unroll
        for (int ntile = 0; ntile < 4; ntile++) {
            int col = n0 + wn * 32 + ntile * 8 + (lane & 3) * 2;
            if (col < VV) {
                float vbx = Vb[col], vby = Vb[col + 1];
                float2 o0 = make_float2(c[im][ntile][0] + vbx, c[im][ntile][1] + vby);
                float2 o1 = make_float2(c[im][ntile][2] + vbx, c[im][ntile][3] + vby);
                *(float2*)(out + (size_t)row * VV + col) = o0;
                *(float2*)(out + (size_t)(row + 8) * VV + col) = o1;
            }
        }
    }
}

// ---------------------------------------------------------------------------
extern "C" void kernel_launch(void* const* d_in, const int* in_sizes, int n_in,
                              void* d_out, int out_size) {
    const float* x  = (const float*)d_in[0];
    const float* Ww = (const float*)d_in[1];
    const float* Wb = (const float*)d_in[2];
    const float* Uw = (const float*)d_in[3];
    const float* Ub = (const float*)d_in[4];
    const float* Vw = (const float*)d_in[5];
    const float* Vb = (const float*)d_in[6];
    float* out = (float*)d_out;

    cudaFuncSetAttribute(k_prep, cudaFuncAttributeMaxDynamicSharedMemorySize, 65536);
    cudaFuncSetAttribute(k_gemm, cudaFuncAttributeMaxDynamicSharedMemorySize,
                         (8192 + 16384) * 4);

    k_prep<<<NT63 + MM / 32, 256, 65536>>>(Vw, x, Uw, Ub, Wb);
    k_rnn<<<BB, 256>>>(Ww, out + (size_t)MM * VV);
    k_gemm<<<dim3(NT63, MT), 256, (8192 + 16384) * 4>>>(Vb, out);
}

// round 11
// speedup vs baseline: 2.2295x; 1.1031x over previous
#include <cuda_runtime.h>
#include <math.h>
#include <stdint.h>

#define BB 32
#define TT 200
#define EE 32
#define HH 128
#define VV 8000
#define MM (BB*TT)            // 6400
#define NT63 63               // n-tiles of 128
#define MT64 100              // 64-row A chunks
#define MT128 50              // m-tiles of 128

// Scratch (device globals)
__device__ float g_ux[MM*HH];              // [m][h]
__device__ float g_Afrag[MT64*8192];       // A fragments (64-row chunks), tf32
__device__ float g_Bfrag[NT63*16384];      // B fragments (128-col tiles), tf32

// ---------------------------------------------------------------------------
__device__ __forceinline__ float to_tf32(float x) {
    unsigned u;
    asm("cvt.rna.tf32.f32 %0, %1;" : "=r"(u) : "f"(x));
    return __uint_as_float(u);
}
__device__ __forceinline__ float tanh_fast(float x) {
    float r;
    asm("tanh.approx.f32 %0, %1;" : "=f"(r) : "f"(x));
    return r;
}
__device__ __forceinline__ void mma8(float c[4], const float4& a, float bx, float by) {
    asm("mma.sync.aligned.m16n8k8.row.col.f32.tf32.tf32.f32 "
        "{%0,%1,%2,%3},{%4,%5,%6,%7},{%8,%9},{%0,%1,%2,%3};"
        : "+f"(c[0]), "+f"(c[1]), "+f"(c[2]), "+f"(c[3])
        : "r"(__float_as_uint(a.x)), "r"(__float_as_uint(a.y)),
          "r"(__float_as_uint(a.z)), "r"(__float_as_uint(a.w)),
          "r"(__float_as_uint(bx)), "r"(__float_as_uint(by)));
}
__device__ __forceinline__ void cpa16(uint32_t s, const void* g) {
    asm volatile("cp.async.ca.shared.global [%0], [%1], 16;" :: "r"(s), "l"(g));
}

// ---------------------------------------------------------------------------
// Fused prep: blocks 0..62 shuffle Vw into B-frag layout; 63..262 compute ux.
// [verified]
// ---------------------------------------------------------------------------
__global__ void k_prep(const float* __restrict__ Vw, const float* __restrict__ x,
                       const float* __restrict__ Uw, const float* __restrict__ Ub,
                       const float* __restrict__ Wb) {
    extern __shared__ float dynsm[];
    int tid = threadIdx.x;
    if (blockIdx.x < NT63) {
        float* Bs = dynsm;                   // 16384 floats
        int nt = blockIdx.x;
        int n0 = nt * 128;
        #pragma unroll
        for (int i = 0; i < 16; i++) {
            int f  = tid + i * 256;
            int nn = f >> 5;
            int c4 = f & 31;
            int gn = n0 + nn;
            float4 v = (gn < VV) ? ((const float4*)Vw)[(size_t)gn * 32 + c4]
                                 : make_float4(0.f, 0.f, 0.f, 0.f);
            int k0 = c4 * 4;
            int kg = k0 >> 3, ip = nn >> 4;
            int reg  = ((nn >> 3) & 1) * 2 + ((k0 & 7) >> 2);
            int base = (kg * 8 + ip) * 128 + ((nn & 7) << 2) * 4 + reg;
            Bs[base + 0]  = to_tf32(v.x);
            Bs[base + 4]  = to_tf32(v.y);
            Bs[base + 8]  = to_tf32(v.z);
            Bs[base + 12] = to_tf32(v.w);
        }
        __syncthreads();
        float4* dst = (float4*)g_Bfrag + (size_t)nt * 4096;
        #pragma unroll
        for (int i = 0; i < 16; i++)
            dst[tid + i * 256] = ((float4*)Bs)[tid + i * 256];
    } else {
        __shared__ float UwT[EE][HH];
        __shared__ float xs[32][EE];
        __shared__ float bias[HH];
        for (int f = tid; f < HH * EE / 4; f += 256) {
            int h = f / (EE / 4), c = f % (EE / 4);
            float4 u = ((const float4*)Uw)[f];
            UwT[c * 4 + 0][h] = u.x;
            UwT[c * 4 + 1][h] = u.y;
            UwT[c * 4 + 2][h] = u.z;
            UwT[c * 4 + 3][h] = u.w;
        }
        if (tid < HH) bias[tid] = Ub[tid] + Wb[tid];
        int m0 = (blockIdx.x - NT63) * 32;
        {
            int r = tid / 8, c = tid % 8;
            ((float4*)&xs[r][0])[c] = ((const float4*)x)[(size_t)(m0 + r) * (EE / 4) + c];
        }
        __syncthreads();
        int h = tid % HH;
        int half = tid / HH;
        #pragma unroll
        for (int rr = 0; rr < 16; rr++) {
            int r = half * 16 + rr;
            float acc = bias[h];
            const float4* xv = (const float4*)&xs[r][0];
            #pragma unroll
            for (int e4 = 0; e4 < EE / 4; e4++) {
                float4 xf = xv[e4];
                acc += UwT[e4 * 4 + 0][h] * xf.x;
                acc += UwT[e4 * 4 + 1][h] * xf.y;
                acc += UwT[e4 * 4 + 2][h] * xf.z;
                acc += UwT[e4 * 4 + 3][h] * xf.w;
            }
            g_ux[(size_t)(m0 + r) * HH + h] = acc;
        }
    }
}

// ---------------------------------------------------------------------------
// Recurrence: R9 exact (verified).
// ---------------------------------------------------------------------------
__global__ void __launch_bounds__(256, 1)
k_rnn(const float* __restrict__ Ww, float* __restrict__ out_hidden) {
    __shared__ float hb[2][HH];
    int tid  = threadIdx.x;
    int j    = tid >> 1;
    int half = tid & 1;
    int b    = blockIdx.x;

    float4 w[16];
    const float4* Ww4 = (const float4*)Ww;
    #pragma unroll
    for (int i = 0; i < 16; i++)
        w[i] = Ww4[(size_t)j * 32 + half * 16 + i];

    if (half == 0) hb[0][j] = 0.0f;
    __syncthreads();

    const float* uxb = g_ux + (size_t)b * TT * HH;

    int kg = j >> 3, kl = j & 7;
    int kcol = (kl & 3) * 4 + 2 * (kl >> 2);

    float uxr = uxb[j];
    int p = 0;
    float v = 0.0f;
    for (int t = 0; t < TT; t++) {
        const float4* h4 = (const float4*)hb[p] + half * 16;
        int tn = (t + 1 < TT) ? t + 1 : t;
        float uxn = uxb[tn * HH + j];

        float a = 0.f, b2 = 0.f, c = 0.f, d = 0.f;
        #pragma unroll
        for (int i = 0; i < 16; i++) {
            float4 hv = h4[i];
            a  += w[i].x * hv.x;
            b2 += w[i].y * hv.y;
            c  += w[i].z * hv.z;
            d  += w[i].w * hv.w;
        }
        float acc = (a + b2) + (c + d);
        acc += __shfl_xor_sync(0xFFFFFFFFu, acc, 1);
        v = tanh_fast(acc + uxr);
        uxr = uxn;
        if (half == 0) {
            hb[1 - p][j] = v;
            int m  = b * TT + t;
            int mt = m >> 6, mr = m & 63;
            int im = mr >> 4, r = mr & 15;
            int idx = mt * 8192 + (kg * 4 + im) * 128
                    + ((r & 7) << 4) + kcol + (r >> 3);
            g_Afrag[idx] = to_tf32(v);
        }
        __syncthreads();
        p ^= 1;
    }
    if (half == 0) out_hidden[b * HH + j] = v;
}

// ---------------------------------------------------------------------------
// Output GEMM: BM=128, BN=128. B in SMEM (64KB, 2 CTAs/SM); A direct LDG.128
// from g_Afrag (lane-linear -> coalesced, L1-cached across the 4 N-warps).
// 8 warps = 2M x 4N, warp tile 64x32, c[4][4][4] (epilogue mapping R7-verified).
// ---------------------------------------------------------------------------
__global__ void __launch_bounds__(256, 2)
k_gemm(const float* __restrict__ Vb, float* __restrict__ out) {
    extern __shared__ float4 Bs4[];       // 4096 float4 (64 KB)

    int tid  = threadIdx.x;
    __builtin_assume(tid >= 0 && tid < 256);
    int warp = tid >> 5;
    int lane = tid & 31;
    int nt = blockIdx.x, mt = blockIdx.y;

    // load B tile via cp.async
    const float4* Bsrc = (const float4*)g_Bfrag + (size_t)nt * 4096;
    uint32_t sB = (uint32_t)__cvta_generic_to_shared(Bs4);
    #pragma unroll
    for (int i = 0; i < 16; i++)
        cpa16(sB + (tid + i * 256) * 16, Bsrc + tid + i * 256);
    asm volatile("cp.async.commit_group;");

    int wm = warp >> 2;   // 0..1  (64-row chunk)
    int wn = warp & 3;    // 0..3  (32-col group)

    // A source for this warp: 64-row chunk (2*mt + wm), lane-linear float4
    const float4* Aw = (const float4*)g_Afrag + (size_t)(2 * mt + wm) * 2048 + lane;

    float c[4][4][4];
    #pragma unroll
    for (int a = 0; a < 4; a++)
        #pragma unroll
        for (int b = 0; b < 4; b++)
            #pragma unroll
            for (int d = 0; d < 4; d++) c[a][b][d] = 0.0f;

    // prefetch kg=0 A fragments
    float4 a_cur[4], a_nxt[4];
    #pragma unroll
    for (int im = 0; im < 4; im++)
        a_cur[im] = Aw[im * 32];

    asm volatile("cp.async.wait_group 0;");
    __syncthreads();

    #pragma unroll
    for (int kg = 0; kg < 16; kg++) {
        if (kg < 15) {
            #pragma unroll
            for (int im = 0; im < 4; im++)
                a_nxt[im] = Aw[((kg + 1) * 4 + im) * 32];
        }
        float4 b0 = Bs4[(kg * 8 + wn * 2 + 0) * 32 + lane];
        float4 b1 = Bs4[(kg * 8 + wn * 2 + 1) * 32 + lane];
        #pragma unroll
        for (int im = 0; im < 4; im++) {
            mma8(c[im][0], a_cur[im], b0.x, b0.y);
            mma8(c[im][1], a_cur[im], b0.z, b0.w);
            mma8(c[im][2], a_cur[im], b1.x, b1.y);
            mma8(c[im][3], a_cur[im], b1.z, b1.w);
        }
        #pragma unroll
        for (int im = 0; im < 4; im++) a_cur[im] = a_nxt[im];
    }

    // epilogue (R7-verified mapping)
    int m0 = mt * 128 + wm * 64;
    int n0 = nt * 128 + wn * 32;
    #pragma unroll
    for (int nt4 = 0; nt4 < 4; nt4++) {
        int col = n0 + nt4 * 8 + (lane & 3) * 2;
        if (col < VV) {
            float vbx = Vb[col], vby = Vb[col + 1];
            #pragma unroll
            for (int im = 0; im < 4; im++) {
                int row = m0 + im * 16 + (lane >> 2);
                float2 o0 = make_float2(c[im][nt4][0] + vbx, c[im][nt4][1] + vby);
                float2 o1 = make_float2(c[im][nt4][2] + vbx, c[im][nt4][3] + vby);
                *(float2*)(out + (size_t)row * VV + col) = o0;
                *(float2*)(out + (size_t)(row + 8) * VV + col) = o1;
            }
        }
    }
}

// ---------------------------------------------------------------------------
extern "C" void kernel_launch(void* const* d_in, const int* in_sizes, int n_in,
                              void* d_out, int out_size) {
    const float* x  = (const float*)d_in[0];
    const float* Ww = (const float*)d_in[1];
    const float* Wb = (const float*)d_in[2];
    const float* Uw = (const float*)d_in[3];
    const float* Ub = (const float*)d_in[4];
    const float* Vw = (const float*)d_in[5];
    const float* Vb = (const float*)d_in[6];
    float* out = (float*)d_out;

    cudaFuncSetAttribute(k_prep, cudaFuncAttributeMaxDynamicSharedMemorySize, 65536);
    cudaFuncSetAttribute(k_gemm, cudaFuncAttributeMaxDynamicSharedMemorySize, 65536);

    k_prep<<<NT63 + MM / 32, 256, 65536>>>(Vw, x, Uw, Ub, Wb);
    k_rnn<<<BB, 256>>>(Ww, out + (size_t)MM * VV);
    k_gemm<<<dim3(NT63, MT128), 256, 65536>>>(Vb, out);
}

// round 12
// speedup vs baseline: 2.2554x; 1.0116x over previous
#include <cuda_runtime.h>
#include <math.h>
#include <stdint.h>

#define BB 32
#define TT 200
#define EE 32
#define HH 128
#define VV 8000
#define MM (BB*TT)            // 6400
#define NT63 63               // 128-col B frag tiles
#define NT64 125              // 64-col gemm n-tiles (exact: 125*64=8000)
#define MT64 100              // 64-row A chunks
#define MT128 50              // 128-row gemm m-tiles

// Scratch (device globals)
__device__ float g_ux[MM*HH];              // [m][h]
__device__ float g_Afrag[MT64*8192];       // A fragments (64-row chunks), tf32
__device__ float g_Bfrag[NT63*16384];      // B fragments (128-col tiles), tf32

// ---------------------------------------------------------------------------
__device__ __forceinline__ float to_tf32(float x) {
    unsigned u;
    asm("cvt.rna.tf32.f32 %0, %1;" : "=r"(u) : "f"(x));
    return __uint_as_float(u);
}
__device__ __forceinline__ float tanh_fast(float x) {
    float r;
    asm("tanh.approx.f32 %0, %1;" : "=f"(r) : "f"(x));
    return r;
}
__device__ __forceinline__ void mma8(float c[4], const float4& a, float bx, float by) {
    asm("mma.sync.aligned.m16n8k8.row.col.f32.tf32.tf32.f32 "
        "{%0,%1,%2,%3},{%4,%5,%6,%7},{%8,%9},{%0,%1,%2,%3};"
        : "+f"(c[0]), "+f"(c[1]), "+f"(c[2]), "+f"(c[3])
        : "r"(__float_as_uint(a.x)), "r"(__float_as_uint(a.y)),
          "r"(__float_as_uint(a.z)), "r"(__float_as_uint(a.w)),
          "r"(__float_as_uint(bx)), "r"(__float_as_uint(by)));
}
__device__ __forceinline__ void cpa16(uint32_t s, const void* g) {
    asm volatile("cp.async.ca.shared.global [%0], [%1], 16;" :: "r"(s), "l"(g));
}

// ---------------------------------------------------------------------------
// ux[m][h] = sum_e x[m][e]*Uw[h][e] + Ub[h] + Wb[h]  [verified]
// ---------------------------------------------------------------------------
__global__ void k_ux(const float* __restrict__ x, const float* __restrict__ Uw,
                     const float* __restrict__ Ub, const float* __restrict__ Wb) {
    __shared__ float UwT[EE][HH];
    __shared__ float xs[32][EE];
    __shared__ float bias[HH];
    int tid = threadIdx.x;

    for (int f = tid; f < HH * EE / 4; f += 256) {
        int h = f / (EE / 4), c = f % (EE / 4);
        float4 u = ((const float4*)Uw)[f];
        UwT[c * 4 + 0][h] = u.x;
        UwT[c * 4 + 1][h] = u.y;
        UwT[c * 4 + 2][h] = u.z;
        UwT[c * 4 + 3][h] = u.w;
    }
    if (tid < HH) bias[tid] = Ub[tid] + Wb[tid];
    int m0 = blockIdx.x * 32;
    {
        int r = tid / 8, c = tid % 8;
        ((float4*)&xs[r][0])[c] = ((const float4*)x)[(size_t)(m0 + r) * (EE / 4) + c];
    }
    __syncthreads();
    int h = tid % HH;
    int half = tid / HH;
    #pragma unroll
    for (int rr = 0; rr < 16; rr++) {
        int r = half * 16 + rr;
        float acc = bias[h];
        const float4* xv = (const float4*)&xs[r][0];
        #pragma unroll
        for (int e4 = 0; e4 < EE / 4; e4++) {
            float4 xf = xv[e4];
            acc += UwT[e4 * 4 + 0][h] * xf.x;
            acc += UwT[e4 * 4 + 1][h] * xf.y;
            acc += UwT[e4 * 4 + 2][h] * xf.z;
            acc += UwT[e4 * 4 + 3][h] * xf.w;
        }
        g_ux[(size_t)(m0 + r) * HH + h] = acc;
    }
}

// ---------------------------------------------------------------------------
// Combined: blocks 0..31 = recurrence (R9-exact, verified);
//           blocks 32..94 = prepB tiles (verified formulas) — overlap for free.
// ---------------------------------------------------------------------------
__global__ void __launch_bounds__(256, 1)
k_rnnprep(const float* __restrict__ Ww, const float* __restrict__ Vw,
          float* __restrict__ out_hidden) {
    extern __shared__ float dynsm[];
    int tid = threadIdx.x;

    if (blockIdx.x >= BB) {
        // ---- prepB ----
        float* Bs = dynsm;                   // 16384 floats
        int nt = blockIdx.x - BB;
        int n0 = nt * 128;
        #pragma unroll
        for (int i = 0; i < 16; i++) {
            int f  = tid + i * 256;
            int nn = f >> 5;
            int c4 = f & 31;
            int gn = n0 + nn;
            float4 v = (gn < VV) ? ((const float4*)Vw)[(size_t)gn * 32 + c4]
                                 : make_float4(0.f, 0.f, 0.f, 0.f);
            int k0 = c4 * 4;
            int kg = k0 >> 3, ip = nn >> 4;
            int reg  = ((nn >> 3) & 1) * 2 + ((k0 & 7) >> 2);
            int base = (kg * 8 + ip) * 128 + ((nn & 7) << 2) * 4 + reg;
            Bs[base + 0]  = to_tf32(v.x);
            Bs[base + 4]  = to_tf32(v.y);
            Bs[base + 8]  = to_tf32(v.z);
            Bs[base + 12] = to_tf32(v.w);
        }
        __syncthreads();
        float4* dst = (float4*)g_Bfrag + (size_t)nt * 4096;
        #pragma unroll
        for (int i = 0; i < 16; i++)
            dst[tid + i * 256] = ((float4*)Bs)[tid + i * 256];
        return;
    }

    // ---- recurrence (R9 exact) ----
    __shared__ float hb[2][HH];
    int j    = tid >> 1;
    int half = tid & 1;
    int b    = blockIdx.x;

    float4 w[16];
    const float4* Ww4 = (const float4*)Ww;
    #pragma unroll
    for (int i = 0; i < 16; i++)
        w[i] = Ww4[(size_t)j * 32 + half * 16 + i];

    if (half == 0) hb[0][j] = 0.0f;
    __syncthreads();

    const float* uxb = g_ux + (size_t)b * TT * HH;

    int kg = j >> 3, kl = j & 7;
    int kcol = (kl & 3) * 4 + 2 * (kl >> 2);

    float uxr = uxb[j];
    int p = 0;
    float v = 0.0f;
    for (int t = 0; t < TT; t++) {
        const float4* h4 = (const float4*)hb[p] + half * 16;
        int tn = (t + 1 < TT) ? t + 1 : t;
        float uxn = uxb[tn * HH + j];

        float a = 0.f, b2 = 0.f, c = 0.f, d = 0.f;
        #pragma unroll
        for (int i = 0; i < 16; i++) {
            float4 hv = h4[i];
            a  += w[i].x * hv.x;
            b2 += w[i].y * hv.y;
            c  += w[i].z * hv.z;
            d  += w[i].w * hv.w;
        }
        float acc = (a + b2) + (c + d);
        acc += __shfl_xor_sync(0xFFFFFFFFu, acc, 1);
        v = tanh_fast(acc + uxr);
        uxr = uxn;
        if (half == 0) {
            hb[1 - p][j] = v;
            int m  = b * TT + t;
            int mt = m >> 6, mr = m & 63;
            int im = mr >> 4, r = mr & 15;
            int idx = mt * 8192 + (kg * 4 + im) * 128
                    + ((r & 7) << 4) + kcol + (r >> 3);
            g_Afrag[idx] = to_tf32(v);
        }
        __syncthreads();
        p ^= 1;
    }
    if (half == 0) out_hidden[b * HH + j] = v;
}

// ---------------------------------------------------------------------------
// Output GEMM: BM=128, BN=64, occupancy 4. 8 warps = 4M x 2N, warp tile 32x32
// (32 accs). A direct lane-linear LDG.128; B = 32KB half-slice of B frags.
// ---------------------------------------------------------------------------
__global__ void __launch_bounds__(256, 4)
k_gemm(const float* __restrict__ Vb, float* __restrict__ out) {
    extern __shared__ float4 Bs4[];       // 2048 float4 (32 KB)

    int tid  = threadIdx.x;
    __builtin_assume(tid >= 0 && tid < 256);
    int warp = tid >> 5;
    int lane = tid & 31;
    int nt = blockIdx.x;                  // 0..124 (64-col tiles)
    int mt = blockIdx.y;                  // 0..49

    // B: copy 4-ip slice (cols nt*64..nt*64+63) of 128-col frag tile nt>>1
    const float4* Bsrc = (const float4*)g_Bfrag + (size_t)(nt >> 1) * 4096
                       + (size_t)(nt & 1) * 4 * 32;
    uint32_t sB = (uint32_t)__cvta_generic_to_shared(Bs4);
    #pragma unroll
    for (int i = 0; i < 8; i++) {
        int f = tid + i * 256;            // 0..2047
        int kg = f >> 7, ipl = (f >> 5) & 3, l = f & 31;
        cpa16(sB + f * 16, Bsrc + (kg * 8 + ipl) * 32 + l);
    }
    asm volatile("cp.async.commit_group;");

    int wm = warp >> 1;   // 0..3 (32-row group)
    int wn = warp & 1;    // 0..1 (32-col group)

    // A: chunk (2*mt + (wm>>1)), im base (wm&1)*2
    const float4* Aw = (const float4*)g_Afrag + (size_t)(2 * mt + (wm >> 1)) * 2048
                     + ((wm & 1) * 2) * 32 + lane;

    float c[2][4][4];
    #pragma unroll
    for (int a = 0; a < 2; a++)
        #pragma unroll
        for (int b = 0; b < 4; b++)
            #pragma unroll
            for (int d = 0; d < 4; d++) c[a][b][d] = 0.0f;

    // prefetch kg=0 A
    float4 a_cur[2], a_nxt[2];
    a_cur[0] = Aw[0];
    a_cur[1] = Aw[32];

    asm volatile("cp.async.wait_group 0;");
    __syncthreads();

    #pragma unroll
    for (int kg = 0; kg < 16; kg++) {
        if (kg < 15) {
            a_nxt[0] = Aw[(kg + 1) * 128];
            a_nxt[1] = Aw[(kg + 1) * 128 + 32];
        }
        float4 b0 = Bs4[(kg * 4 + wn * 2 + 0) * 32 + lane];
        float4 b1 = Bs4[(kg * 4 + wn * 2 + 1) * 32 + lane];
        #pragma unroll
        for (int im = 0; im < 2; im++) {
            mma8(c[im][0], a_cur[im], b0.x, b0.y);
            mma8(c[im][1], a_cur[im], b0.z, b0.w);
            mma8(c[im][2], a_cur[im], b1.x, b1.y);
            mma8(c[im][3], a_cur[im], b1.z, b1.w);
        }
        a_cur[0] = a_nxt[0];
        a_cur[1] = a_nxt[1];
    }

    // epilogue (verified fragment mapping; no bounds needed: 125*64 == 8000)
    int m0 = mt * 128 + wm * 32;
    int n0 = nt * 64 + wn * 32;
    #pragma unroll
    for (int nt4 = 0; nt4 < 4; nt4++) {
        int col = n0 + nt4 * 8 + (lane & 3) * 2;
        float vbx = Vb[col], vby = Vb[col + 1];
        #pragma unroll
        for (int im = 0; im < 2; im++) {
            int row = m0 + im * 16 + (lane >> 2);
            float2 o0 = make_float2(c[im][nt4][0] + vbx, c[im][nt4][1] + vby);
            float2 o1 = make_float2(c[im][nt4][2] + vbx, c[im][nt4][3] + vby);
            *(float2*)(out + (size_t)row * VV + col) = o0;
            *(float2*)(out + (size_t)(row + 8) * VV + col) = o1;
        }
    }
}

// ---------------------------------------------------------------------------
extern "C" void kernel_launch(void* const* d_in, const int* in_sizes, int n_in,
                              void* d_out, int out_size) {
    const float* x  = (const float*)d_in[0];
    const float* Ww = (const float*)d_in[1];
    const float* Wb = (const float*)d_in[2];
    const float* Uw = (const float*)d_in[3];
    const float* Ub = (const float*)d_in[4];
    const float* Vw = (const float*)d_in[5];
    const float* Vb = (const float*)d_in[6];
    float* out = (float*)d_out;

    cudaFuncSetAttribute(k_rnnprep, cudaFuncAttributeMaxDynamicSharedMemorySize, 65536);
    cudaFuncSetAttribute(k_gemm,    cudaFuncAttributeMaxDynamicSharedMemorySize, 32768);

    k_ux<<<MM / 32, 256>>>(x, Uw, Ub, Wb);
    k_rnnprep<<<BB + NT63, 256, 65536>>>(Ww, Vw, out + (size_t)MM * VV);
    k_gemm<<<dim3(NT64, MT128), 256, 32768>>>(Vb, out);
}